// round 17
// baseline (speedup 1.0000x reference)
#include <cuda_runtime.h>

#define TT   2048
#define HB   128
#define NL   3
#define GCTA 32    // H-CTAs per layer
#define NJ   4
#define NR   16    // gate rows per H-CTA
#define XCTA 16    // X-CTAs per layer (layers 1,2)
#define XR   32    // gate rows per X-CTA
#define PD   8     // P ring depth

// h history, PAIR-PACKED: (l, slot, j, b) at ((l*(TT+1)+slot)*64 + (j>>1))*256 + b*2 + (j&1)
__device__ __align__(16) float g_H[(size_t)NL * (TT + 1) * HB * HB];
// x transposed, pair-packed: (t, i, b) at (t*4 + (i>>1))*256 + b*2 + (i&1), i pad 6->8
__device__ __align__(16) float g_xT[TT * 8 * HB];
// P ring: [xl(2)][slot(8)][R(512)][b(128)]  = 2 MB (L2-resident)
__device__ __align__(16) float g_P[2 * PD * 512 * HB];
// H weights: L0 [32][16][136] (8 x-cols + 128 h); L1/2 [32][16][128] (hh only)
#define HO0 0
#define HO1 (GCTA*NR*136)
#define HO2 (HO1 + GCTA*NR*128)
__device__ float g_WpH[HO2 + GCTA*NR*128];
// X weights: [xl(2)][xg(16)][r(32)][k(128)], r = q*8+j <-> R = q*128 + xg*8 + j
__device__ float g_WpX[2 * XCTA * XR * 128];
__device__ float g_bias[NL * GCTA * NR];
__device__ __align__(128) int g_flagsH[NL * 32];   // completed steps per H-CTA
__device__ __align__(128) int g_flagsX[2 * 32];    // completed steps per X-CTA (16 used/line)

typedef unsigned long long ull;

__device__ __forceinline__ ull pk2(float lo, float hi) {
    ull r; asm("mov.b64 %0,{%1,%2};" : "=l"(r) : "f"(lo), "f"(hi)); return r;
}
__device__ __forceinline__ float sum2(ull v) {
    float lo, hi; asm("mov.b64 {%0,%1},%2;" : "=f"(lo), "=f"(hi) : "l"(v));
    return lo + hi;
}
__device__ __forceinline__ ull ffma2(ull a, ull b, ull c) {
    ull d; asm("fma.rn.f32x2 %0,%1,%2,%3;" : "=l"(d) : "l"(a), "l"(b), "l"(c));
    return d;
}
__device__ __forceinline__ int ldacq(const int* p) {
    int v; asm volatile("ld.acquire.gpu.global.b32 %0,[%1];" : "=r"(v) : "l"(p) : "memory");
    return v;
}
__device__ __forceinline__ void strel(int* p, int v) {
    asm volatile("st.release.gpu.global.b32 [%0],%1;" :: "l"(p), "r"(v) : "memory");
}
__device__ __forceinline__ float sigf(float x) {
    return __fdividef(1.0f, 1.0f + __expf(-x));
}
__device__ __forceinline__ float tanhf_fast(float x) {
    return __fdividef(2.0f, 1.0f + __expf(-2.0f * x)) - 1.0f;
}
// ONE warp: wait until fl[0..n-1] >= t (lanes >= n auto-pass).
__device__ __forceinline__ void spinN(const int* fl, int t, int lane, int n) {
    for (;;) {
        int f = (lane < n) ? ldacq(fl + lane) : t;
        if (__ballot_sync(0xffffffffu, f < t) == 0u) break;
    }
}

// ============ setup ============
__global__ void setup_kernel(
    const float* __restrict__ x,
    const float* __restrict__ Wih0, const float* __restrict__ Whh0,
    const float* __restrict__ bih0, const float* __restrict__ bhh0,
    const float* __restrict__ Wih1, const float* __restrict__ Whh1,
    const float* __restrict__ bih1, const float* __restrict__ bhh1,
    const float* __restrict__ Wih2, const float* __restrict__ Whh2,
    const float* __restrict__ bih2, const float* __restrict__ bhh2)
{
    int blk = blockIdx.x, tid = threadIdx.x;
    if (blk < NL * GCTA) {                       // H weights + bias
        int l = blk / GCTA, g = blk % GCTA;
        const float* Whh = (l == 0) ? Whh0 : ((l == 1) ? Whh1 : Whh2);
        const float* bih = (l == 0) ? bih0 : ((l == 1) ? bih1 : bih2);
        const float* bhh = (l == 0) ? bhh0 : ((l == 1) ? bhh1 : bhh2);
        int KP = (l == 0) ? 136 : 128;
        int base = ((l == 0) ? HO0 : ((l == 1) ? HO1 : HO2)) + g * NR * KP;
        for (int idx = tid; idx < NR * KP; idx += blockDim.x) {
            int r = idx / KP, k = idx % KP;
            int R = (r >> 2) * 128 + g * NJ + (r & 3);
            float v;
            if (l == 0) v = (k < 8) ? ((k < 6) ? Wih0[R * 6 + k] : 0.0f)
                                    : Whh[R * 128 + (k - 8)];
            else        v = Whh[R * 128 + k];
            g_WpH[base + idx] = v;
        }
        if (tid < NR) {
            int R = (tid >> 2) * 128 + g * NJ + (tid & 3);
            g_bias[(l * GCTA + g) * NR + tid] = bih[R] + bhh[R];
        }
        if (blk == 0) {
            if (tid < NL * 32) g_flagsH[tid] = 0;
            if (tid < 2 * 32)  g_flagsX[tid] = 0;
        }
    } else if (blk < NL * GCTA + 2 * XCTA) {     // X weights
        int xi = blk - NL * GCTA;
        int xl = xi >> 4, xg = xi & 15;
        const float* Wih = (xl == 0) ? Wih1 : Wih2;
        for (int idx = tid; idx < XR * 128; idx += blockDim.x) {
            int r = idx >> 7, k = idx & 127;
            int R = (r >> 3) * 128 + xg * 8 + (r & 7);
            g_WpX[(xl * XCTA + xg) * XR * 128 + idx] = Wih[R * 128 + k];
        }
    } else if (blk < NL * GCTA + 2 * XCTA + TT) { // x transpose
        int t = blk - NL * GCTA - 2 * XCTA;
        if (tid < HB) {
            #pragma unroll
            for (int i = 0; i < 8; i++) {
                float v = (i < 6) ? x[(size_t)tid * (TT * 6) + t * 6 + i] : 0.0f;
                g_xT[(t * 4 + (i >> 1)) * 256 + tid * 2 + (i & 1)] = v;
            }
        }
    } else {                                      // zero h slot 0 per layer
        size_t base = (size_t)(blk - NL * GCTA - 2 * XCTA - TT) * (TT + 1) * HB * HB;
        for (int i = tid; i < HB * HB; i += blockDim.x) g_H[base + i] = 0.0f;
    }
}

// ---- GEMM: NG groups of 4 cols, 16 rows, 2 batch cols (b0, b0+32 baked into p).
template<int KP, int NG>
__device__ __forceinline__ void gemm2b(const float2* __restrict__ p,
                                       const float* __restrict__ wb,
                                       ull* acc /*32*/)
{
    #pragma unroll
    for (int i = 0; i < NG; i++) {
        float2 a01 = __ldcg(p + (2 * i) * 128);
        float2 a23 = __ldcg(p + (2 * i + 1) * 128);
        float2 e01 = __ldcg(p + (2 * i) * 128 + 32);
        float2 e23 = __ldcg(p + (2 * i + 1) * 128 + 32);
        ull h01 = pk2(a01.x, a01.y), h23 = pk2(a23.x, a23.y);
        ull g01 = pk2(e01.x, e01.y), g23 = pk2(e23.x, e23.y);
        const float* w0 = wb + 4 * i;
        #pragma unroll
        for (int r = 0; r < NR; r++) {
            ulonglong2 w = *(const ulonglong2*)(w0 + r * KP);  // LDS.128 bcast
            acc[r]      = ffma2(w.x, h01, acc[r]);
            acc[r]      = ffma2(w.y, h23, acc[r]);
            acc[NR + r] = ffma2(w.x, g01, acc[NR + r]);
            acc[NR + r] = ffma2(w.y, g23, acc[NR + r]);
        }
    }
}

// ---- H body: hh GEMM (K=128) + P add. 512 thr: warp = kq(8)*bg(2), 2 b/thread.
template<int L>
__device__ __forceinline__ void h_run(int g, float* Wsm, float* RD, float* bsm)
{
    constexpr int KP = (L == 0) ? 136 : 128;
    constexpr int WO = (L == 0) ? HO0 : ((L == 1) ? HO1 : HO2);

    const int tid  = threadIdx.x;
    const int lane = tid & 31;
    const int warp = tid >> 5;
    const int bg   = warp & 1;
    const int kq   = warp >> 1;          // 0..7
    const int b0   = bg * 64 + lane;
    const int jj   = tid >> 7;           // 0..3
    const int be   = tid & 127;
    const int jrow = g * NJ + jj;

    for (int i = tid; i < NR * KP; i += 512) Wsm[i] = g_WpH[WO + g * NR * KP + i];
    if (tid < NR) bsm[tid] = g_bias[(L * GCTA + g) * NR + tid];
    __syncthreads();

    int* ownf = g_flagsH + L * 32;
    float c = 0.0f;

    for (int t = 0; t < TT; t++) {
        if (warp == 0) spinN(ownf, t, lane, 32);
        if (L > 0 && warp == 1) spinN(g_flagsX + (L - 1) * 32, t + 1, lane, XCTA);
        __syncthreads();

        // prefetch P partials (epilogue-only use)
        float p0 = 0, p1 = 0, p2 = 0, p3 = 0;
        if (L > 0) {
            const float* Pb = g_P + (((L - 1) * PD + (t & (PD - 1))) * 512) * HB;
            p0 = __ldcg(Pb + (0 * 128 + jrow) * HB + be);
            p1 = __ldcg(Pb + (1 * 128 + jrow) * HB + be);
            p2 = __ldcg(Pb + (2 * 128 + jrow) * HB + be);
            p3 = __ldcg(Pb + (3 * 128 + jrow) * HB + be);
        }

        const float2* hb = (const float2*)(g_H + (size_t)(L * (TT + 1) + t) * HB * HB);

        ull acc[2 * NR];
        #pragma unroll
        for (int r = 0; r < 2 * NR; r++) acc[r] = 0ULL;

        if constexpr (L == 0) {
            const float2* xb = (const float2*)(g_xT + (size_t)t * 1024);
            if (kq == 0) {
                gemm2b<KP, 2>(xb + b0, Wsm, acc);                 // x cols 0..7
                gemm2b<KP, 4>(hb + b0, Wsm + 8, acc);             // h cols 0..15
            } else {
                gemm2b<KP, 4>(hb + (8 * kq) * 128 + b0, Wsm + 8 + 16 * kq, acc);
            }
        } else {
            gemm2b<KP, 4>(hb + (8 * kq) * 128 + b0, Wsm + 16 * kq, acc);
        }

        #pragma unroll
        for (int r = 0; r < NR; r++) {
            RD[(kq * NR + r) * HB + b0]      = sum2(acc[r]);
            RD[(kq * NR + r) * HB + b0 + 32] = sum2(acc[NR + r]);
        }
        __syncthreads();

        // ---- epilogue: thread (jj, be)
        {
            float v0 = bsm[0 * 4 + jj] + p0, v1 = bsm[1 * 4 + jj] + p1;
            float v2 = bsm[2 * 4 + jj] + p2, v3 = bsm[3 * 4 + jj] + p3;
            #pragma unroll
            for (int q2 = 0; q2 < 8; q2++) {
                v0 += RD[(q2 * NR + 0 * 4 + jj) * HB + be];
                v1 += RD[(q2 * NR + 1 * 4 + jj) * HB + be];
                v2 += RD[(q2 * NR + 2 * 4 + jj) * HB + be];
                v3 += RD[(q2 * NR + 3 * 4 + jj) * HB + be];
            }
            float iv = sigf(v0);
            float fv = sigf(v1);
            float gv = tanhf_fast(v2);
            float ov = sigf(v3);
            c = fv * c + iv * gv;
            float* Hout = g_H + (size_t)(L * (TT + 1) + t + 1) * HB * HB;
            __stcg(Hout + (jrow >> 1) * 256 + be * 2 + (jrow & 1),
                   ov * tanhf_fast(c));
        }
        __syncthreads();
        if (tid == 0) strel(ownf + g, t + 1);
    }
}

// ---- X body: P_L(t) = W_ih(L) @ h_{L-1}(t). 512 thr: warp = kq(4)*bg(4), 1 b/thr.
__device__ void x_run(int xl, int xg, float* Wsm, float* RDx)
{
    const int tid  = threadIdx.x;
    const int lane = tid & 31;
    const int warp = tid >> 5;
    const int bg   = warp & 3;
    const int kq   = warp >> 2;          // 0..3 (32 cols each)
    const int b    = bg * 32 + lane;

    for (int i = tid; i < XR * 128; i += 512)
        Wsm[i] = g_WpX[(xl * XCTA + xg) * XR * 128 + i];
    __syncthreads();

    const int sr = tid >> 4;             // stage2: local row 0..31
    const int sb = (tid & 15) * 8;
    const int sR = (sr >> 3) * 128 + xg * 8 + (sr & 7);

    for (int t = 0; t < TT; t++) {
        if (warp == 0) spinN(g_flagsH + xl * 32, t + 1, lane, 32);       // below h(t)
        if (warp == 1) spinN(g_flagsH + (xl + 1) * 32, t - 6, lane, 32); // ring backpressure
        __syncthreads();

        const float2* hb = (const float2*)(g_H + (size_t)(xl * (TT + 1) + t + 1) * HB * HB);

        ull acc[XR];
        #pragma unroll
        for (int r = 0; r < XR; r++) acc[r] = 0ULL;

        #pragma unroll
        for (int grp = 0; grp < 8; grp++) {          // 32 cols = 16 jp
            int jp0 = kq * 16 + 2 * grp;
            ull h01, h23;
            {
                float2 a = __ldcg(hb + jp0 * 128 + b);
                float2 e = __ldcg(hb + (jp0 + 1) * 128 + b);
                h01 = pk2(a.x, a.y); h23 = pk2(e.x, e.y);
            }
            const float* w0 = Wsm + kq * 32 + 4 * grp;
            #pragma unroll
            for (int r = 0; r < XR; r++) {
                ulonglong2 w = *(const ulonglong2*)(w0 + r * 128);
                acc[r] = ffma2(w.x, h01, acc[r]);
                acc[r] = ffma2(w.y, h23, acc[r]);
            }
        }

        #pragma unroll
        for (int r = 0; r < XR; r++)
            RDx[(kq * XR + r) * HB + b] = sum2(acc[r]);
        __syncthreads();

        // stage2: sum 4 kq, store to P ring
        float* Pout = g_P + (((xl * PD + (t & (PD - 1))) * 512 + sR)) * HB;
        {
            const float* r0 = RDx + (0 * XR + sr) * HB + sb;
            const float* r1 = RDx + (1 * XR + sr) * HB + sb;
            const float* r2 = RDx + (2 * XR + sr) * HB + sb;
            const float* r3 = RDx + (3 * XR + sr) * HB + sb;
            #pragma unroll
            for (int m = 0; m < 8; m++)
                __stcg(Pout + sb + m, r0[m] + r1[m] + r2[m] + r3[m]);
        }
        __syncthreads();   // RDx reusable + stores ordered before release
        if (tid == 0) strel(&g_flagsX[xl * 32 + xg], t + 1);
    }
}

__global__ void __launch_bounds__(512, 1) lstm_kernel(
    const float* __restrict__ W_out, const float* __restrict__ b_out,
    float* __restrict__ out)
{
    extern __shared__ float sm[];
    const int blk = blockIdx.x;

    if (blk < NL * GCTA) {
        float* Wsm = sm;                        // <= 16*136 floats
        float* RD  = sm + NR * 136;             // 8*16*128 floats (64 KB)
        float* bsm = RD + 8 * NR * HB;
        const int l = blk >> 5, g = blk & 31;
        if (l == 0)      h_run<0>(g, Wsm, RD, bsm);
        else if (l == 1) h_run<1>(g, Wsm, RD, bsm);
        else             h_run<2>(g, Wsm, RD, bsm);

        // head folded into H CTA (l=2, g=0)
        if (blk == 2 * GCTA) {
            if (threadIdx.x < 32) spinN(g_flagsH + 2 * 32, TT, threadIdx.x, 32);
            __syncthreads();
            if (threadIdx.x < HB) {
                const float* h = g_H + (size_t)(2 * (TT + 1) + TT) * HB * HB;
                int b = threadIdx.x;
                float s = b_out[0];
                #pragma unroll 8
                for (int j = 0; j < HB; j++)
                    s += __ldcg(h + (j >> 1) * 256 + b * 2 + (j & 1)) * W_out[j];
                out[b] = s;
            }
        }
    } else {
        float* Wsm = sm;                        // 32*128 floats (16 KB)
        float* RDx = sm + XR * 128;             // 4*32*128 floats (64 KB)
        const int xi = blk - NL * GCTA;
        x_run(xi >> 4, xi & 15, Wsm, RDx);
    }
}

extern "C" void kernel_launch(void* const* d_in, const int* in_sizes, int n_in,
                              void* d_out, int out_size)
{
    (void)in_sizes; (void)n_in; (void)out_size;

    const int SMEM_DYN = (XR * 128 + 4 * XR * HB) * 4 + 256;   // 82,176 B (covers H too)
    cudaFuncSetAttribute(lstm_kernel,
                         cudaFuncAttributeMaxDynamicSharedMemorySize, SMEM_DYN);

    setup_kernel<<<NL * GCTA + 2 * XCTA + TT + NL, 512>>>(
        (const float*)d_in[0],
        (const float*)d_in[1], (const float*)d_in[2],
        (const float*)d_in[3], (const float*)d_in[4],
        (const float*)d_in[5], (const float*)d_in[6],
        (const float*)d_in[7], (const float*)d_in[8],
        (const float*)d_in[9], (const float*)d_in[10],
        (const float*)d_in[11], (const float*)d_in[12]);
    lstm_kernel<<<NL * GCTA + 2 * XCTA, 512, SMEM_DYN>>>(
        (const float*)d_in[13], (const float*)d_in[14], (float*)d_out);
}